// round 1
// baseline (speedup 1.0000x reference)
#include <cuda_runtime.h>
#include <math.h>

#define CHN   12
#define GENE  3
#define OUTC  9      // CHN - GENE
#define HID   128
#define PERC  36
#define HH    256
#define WW    256
#define BB    16

// w2 transposed and padded to 12 floats per hidden unit for float4 loads
#define W2PAD 12

__global__ __launch_bounds__(256) void isoca_kernel(
    const float* __restrict__ x,
    const float* __restrict__ rnd,
    const float* __restrict__ w1_w,
    const float* __restrict__ w1_b,
    const float* __restrict__ w2_w,
    float* __restrict__ out)
{
    __shared__ float w1s[HID * PERC];    // 18432 B, row j = hidden unit j (36 floats, 144B aligned)
    __shared__ float w2ts[HID * W2PAD];  // 6144 B, w2ts[j*12+o] = w2_w[o*128+j]
    __shared__ float b1s[HID];

    const int tid = threadIdx.x;

    // ---- cooperative weight staging ----
    for (int i = tid; i < HID * PERC; i += 256) w1s[i] = w1_w[i];
    for (int i = tid; i < HID * W2PAD; i += 256) {
        int j = i / W2PAD, o = i - j * W2PAD;
        w2ts[i] = (o < OUTC) ? w2_w[o * HID + j] : 0.0f;
    }
    if (tid < HID) b1s[tid] = w1_b[tid];

    const int wc = tid;          // column 0..255 (block = one full image row)
    const int h  = blockIdx.x;   // row
    const int b  = blockIdx.y;   // batch

    const int hm = (h + HH - 1) & (HH - 1);
    const int hp = (h + 1) & (HH - 1);
    const int wm = (wc + WW - 1) & (WW - 1);
    const int wp = (wc + 1) & (WW - 1);

    float perc[PERC];
    float pool = 0.0f;

    const float* xb = x + (size_t)b * CHN * HH * WW;

    #pragma unroll
    for (int c = 0; c < CHN; ++c) {
        const float* xc = xb + (size_t)c * HH * WW;
        const float* rU = xc + hm * WW;
        const float* rC = xc + h  * WW;
        const float* rD = xc + hp * WW;
        float n00 = __ldg(rU + wm), n01 = __ldg(rU + wc), n02 = __ldg(rU + wp);
        float n10 = __ldg(rC + wm), n11 = __ldg(rC + wc), n12 = __ldg(rC + wp);
        float n20 = __ldg(rD + wm), n21 = __ldg(rD + wc), n22 = __ldg(rD + wp);

        // cross-correlation (lax.conv, no flip), circular padding
        float lap = (n00 + n02 + n20 + n22) + 2.0f * (n01 + n10 + n12 + n21) - 12.0f * n11;
        float gx  = (n02 - n00) + 2.0f * (n12 - n10) + (n22 - n20);
        float gy  = (n20 - n00) + 2.0f * (n21 - n01) + (n22 - n02);

        perc[2 * c]     = n11;
        perc[2 * c + 1] = lap;
        perc[2 * CHN + c] = sqrtf(gx * gx + gy * gy + 1e-8f);

        if (c == 3) {
            // 3x3 max-pool with -inf (clamp) padding: wrapped neighbor values
            // equal true values whenever the index is in-bounds, so reuse them.
            bool tu = (h > 0), td = (h < HH - 1), tl = (wc > 0), tr = (wc < WW - 1);
            float p = n11;
            if (tu) p = fmaxf(p, n01);
            if (td) p = fmaxf(p, n21);
            if (tl) p = fmaxf(p, n10);
            if (tr) p = fmaxf(p, n12);
            if (tu && tl) p = fmaxf(p, n00);
            if (tu && tr) p = fmaxf(p, n02);
            if (td && tl) p = fmaxf(p, n20);
            if (td && tr) p = fmaxf(p, n22);
            pool = p;
        }
    }

    __syncthreads();

    // ---- MLP: 36 -> 128 (leaky relu) -> 9, hidden streamed ----
    float acc[OUTC];
    #pragma unroll
    for (int o = 0; o < OUTC; ++o) acc[o] = 0.0f;

    #pragma unroll 2
    for (int j = 0; j < HID; ++j) {
        const float4* w1r = (const float4*)(w1s + j * PERC);
        float s = b1s[j];
        #pragma unroll
        for (int k4 = 0; k4 < PERC / 4; ++k4) {
            float4 wv = w1r[k4];
            int k = k4 * 4;
            s = fmaf(wv.x, perc[k],     s);
            s = fmaf(wv.y, perc[k + 1], s);
            s = fmaf(wv.z, perc[k + 2], s);
            s = fmaf(wv.w, perc[k + 3], s);
        }
        s = (s >= 0.0f) ? s : 0.01f * s;   // leaky relu
        const float4* w2r = (const float4*)(w2ts + j * W2PAD);
        float4 a0 = w2r[0], a1 = w2r[1], a2 = w2r[2];
        acc[0] = fmaf(a0.x, s, acc[0]);
        acc[1] = fmaf(a0.y, s, acc[1]);
        acc[2] = fmaf(a0.z, s, acc[2]);
        acc[3] = fmaf(a0.w, s, acc[3]);
        acc[4] = fmaf(a1.x, s, acc[4]);
        acc[5] = fmaf(a1.y, s, acc[5]);
        acc[6] = fmaf(a1.z, s, acc[6]);
        acc[7] = fmaf(a1.w, s, acc[7]);
        acc[8] = fmaf(a2.x, s, acc[8]);
    }

    // ---- gate + write ----
    const size_t pix = (size_t)h * WW + wc;
    float r = __ldg(rnd + (size_t)b * HH * WW + pix);
    float mask = floorf(r + 0.5f);                 // update mask in {0,1}
    float life = (pool > 0.1f) ? 1.0f : 0.0f;
    float gate = mask * life;

    float* ob = out + (size_t)b * CHN * HH * WW + pix;
    #pragma unroll
    for (int c = 0; c < OUTC; ++c)
        ob[(size_t)c * HH * WW] = perc[2 * c] + acc[c] * gate;
    #pragma unroll
    for (int c = OUTC; c < CHN; ++c)               // gene passthrough
        ob[(size_t)c * HH * WW] = perc[2 * c];
}

extern "C" void kernel_launch(void* const* d_in, const int* in_sizes, int n_in,
                              void* d_out, int out_size) {
    const float* x    = (const float*)d_in[0];
    const float* rnd  = (const float*)d_in[1];
    const float* w1_w = (const float*)d_in[2];
    const float* w1_b = (const float*)d_in[3];
    const float* w2_w = (const float*)d_in[4];
    float* out = (float*)d_out;

    dim3 grid(HH, BB);
    dim3 block(WW);
    isoca_kernel<<<grid, block>>>(x, rnd, w1_w, w1_b, w2_w, out);
}

// round 2
// speedup vs baseline: 1.1494x; 1.1494x over previous
#include <cuda_runtime.h>
#include <math.h>

#define CHN   12
#define GENE  3
#define OUTC  9
#define HID   128
#define PERC  36
#define HH    256
#define WW    256
#define BB    16
#define W2PAD 10          // 9 outputs + 1 pad -> 80B rows (16B aligned)

typedef unsigned long long ull;

__device__ __forceinline__ void fma2(ull &d, ull a, ull b) {
    asm("fma.rn.f32x2 %0, %1, %2, %0;" : "+l"(d) : "l"(a), "l"(b));
}
__device__ __forceinline__ ull add2(ull a, ull b) {
    ull d; asm("add.rn.f32x2 %0, %1, %2;" : "=l"(d) : "l"(a), "l"(b)); return d;
}
__device__ __forceinline__ ull f2u(float lo, float hi) {
    ull d; asm("mov.b64 %0, {%1, %2};" : "=l"(d) : "f"(lo), "f"(hi)); return d;
}
__device__ __forceinline__ float2 u2f(ull v) {
    float2 r; asm("mov.b64 {%0, %1}, %2;" : "=f"(r.x), "=f"(r.y) : "l"(v)); return r;
}

__global__ __launch_bounds__(256, 2) void isoca_kernel(
    const float* __restrict__ x,
    const float* __restrict__ rnd,
    const float* __restrict__ w1_w,
    const float* __restrict__ w1_b,
    const float* __restrict__ w2_w,
    float* __restrict__ out)
{
    // weights pre-duplicated {w,w} so LDS.128 yields 2 packed operands, no MOVs
    __shared__ __align__(16) float2 w1d[HID * PERC];   // 36864 B
    __shared__ __align__(16) float2 w2d[HID * W2PAD];  // 10240 B
    __shared__ ull b1d[HID];                           //  1024 B

    const int tid = threadIdx.x;

    for (int i = tid; i < HID * PERC; i += 256) {
        float w = w1_w[i];
        w1d[i] = make_float2(w, w);
    }
    for (int i = tid; i < HID * W2PAD; i += 256) {
        int j = i / W2PAD, o = i - j * W2PAD;
        float w = (o < OUTC) ? w2_w[o * HID + j] : 0.0f;
        w2d[i] = make_float2(w, w);
    }
    if (tid < HID) {
        float bi = w1_b[tid];
        b1d[tid] = f2u(bi, bi);
    }

    const int wc = tid;
    const int rb = blockIdx.x;          // row pair 0..127
    const int b  = blockIdx.y;
    const int h0 = 2 * rb, h1 = 2 * rb + 1;
    const int hm = (h0 + HH - 1) & (HH - 1);
    const int hp = (h1 + 1) & (HH - 1);
    const int wm = (wc + WW - 1) & (WW - 1);
    const int wp = (wc + 1) & (WW - 1);

    ull P[PERC];
    float poolA = 0.0f, poolB = 0.0f;

    const float* xb = x + (size_t)b * CHN * HH * WW;

    #pragma unroll
    for (int c = 0; c < CHN; ++c) {
        const float* xc = xb + (size_t)c * HH * WW;
        const float* Rm = xc + hm * WW;
        const float* R0 = xc + h0 * WW;
        const float* R1 = xc + h1 * WW;
        const float* Rp = xc + hp * WW;
        float ml = __ldg(Rm + wm), mc = __ldg(Rm + wc), mr = __ldg(Rm + wp);
        float al = __ldg(R0 + wm), ac = __ldg(R0 + wc), ar = __ldg(R0 + wp);
        float bl = __ldg(R1 + wm), bc = __ldg(R1 + wc), br = __ldg(R1 + wp);
        float pl = __ldg(Rp + wm), pc = __ldg(Rp + wc), pr = __ldg(Rp + wp);

        // pixel A (row h0): rows m,0,1 ; pixel B (row h1): rows 0,1,p
        float lapA = (ml + mr + bl + br) + 2.0f * (mc + al + ar + bc) - 12.0f * ac;
        float gxA  = (mr - ml) + 2.0f * (ar - al) + (br - bl);
        float gyA  = (bl - ml) + 2.0f * (bc - mc) + (br - mr);
        float lapB = (al + ar + pl + pr) + 2.0f * (ac + bl + br + pc) - 12.0f * bc;
        float gxB  = (ar - al) + 2.0f * (br - bl) + (pr - pl);
        float gyB  = (pl - al) + 2.0f * (pc - ac) + (pr - ar);

        P[2 * c]       = f2u(ac, bc);
        P[2 * c + 1]   = f2u(lapA, lapB);
        P[2 * CHN + c] = f2u(sqrtf(gxA * gxA + gyA * gyA + 1e-8f),
                             sqrtf(gxB * gxB + gyB * gyB + 1e-8f));

        if (c == 3) {
            bool tl = (wc > 0), tr = (wc < WW - 1);
            float cm = mc; if (tl) cm = fmaxf(cm, ml); if (tr) cm = fmaxf(cm, mr);
            float c0 = ac; if (tl) c0 = fmaxf(c0, al); if (tr) c0 = fmaxf(c0, ar);
            float c1 = bc; if (tl) c1 = fmaxf(c1, bl); if (tr) c1 = fmaxf(c1, br);
            float cp = pc; if (tl) cp = fmaxf(cp, pl); if (tr) cp = fmaxf(cp, pr);
            poolA = fmaxf(c0, c1); if (h0 > 0)      poolA = fmaxf(poolA, cm);
            poolB = fmaxf(c0, c1); if (h1 < HH - 1) poolB = fmaxf(poolB, cp);
        }
    }

    __syncthreads();

    ull acc[OUTC];
    #pragma unroll
    for (int o = 0; o < OUTC; ++o) acc[o] = 0ull;

    #pragma unroll 2
    for (int j = 0; j < HID; ++j) {
        const ulonglong2* w1r = (const ulonglong2*)(w1d + j * PERC);
        ull s[4];
        s[0] = b1d[j]; s[1] = 0ull; s[2] = 0ull; s[3] = 0ull;
        #pragma unroll
        for (int i = 0; i < PERC / 2; ++i) {
            ulonglong2 w = w1r[i];
            fma2(s[(2 * i)     & 3], w.x, P[2 * i]);
            fma2(s[(2 * i + 1) & 3], w.y, P[2 * i + 1]);
        }
        ull sv = add2(add2(s[0], s[1]), add2(s[2], s[3]));
        float2 sf = u2f(sv);
        sf.x = fmaxf(sf.x, 0.0f) + 0.01f * fminf(sf.x, 0.0f);   // leaky relu
        sf.y = fmaxf(sf.y, 0.0f) + 0.01f * fminf(sf.y, 0.0f);
        ull sp = f2u(sf.x, sf.y);

        const ulonglong2* w2r = (const ulonglong2*)(w2d + j * W2PAD);
        ulonglong2 q0 = w2r[0], q1 = w2r[1], q2 = w2r[2], q3 = w2r[3], q4 = w2r[4];
        fma2(acc[0], q0.x, sp); fma2(acc[1], q0.y, sp);
        fma2(acc[2], q1.x, sp); fma2(acc[3], q1.y, sp);
        fma2(acc[4], q2.x, sp); fma2(acc[5], q2.y, sp);
        fma2(acc[6], q3.x, sp); fma2(acc[7], q3.y, sp);
        fma2(acc[8], q4.x, sp);
    }

    // gates
    const float* rb_ptr = rnd + (size_t)b * HH * WW;
    float rA = __ldg(rb_ptr + (size_t)h0 * WW + wc);
    float rB = __ldg(rb_ptr + (size_t)h1 * WW + wc);
    float gateA = floorf(rA + 0.5f) * ((poolA > 0.1f) ? 1.0f : 0.0f);
    float gateB = floorf(rB + 0.5f) * ((poolB > 0.1f) ? 1.0f : 0.0f);

    float* ob = out + (size_t)b * CHN * HH * WW;
    const size_t pA = (size_t)h0 * WW + wc;
    const size_t pB = (size_t)h1 * WW + wc;
    #pragma unroll
    for (int o = 0; o < OUTC; ++o) {
        float2 a  = u2f(acc[o]);
        float2 pv = u2f(P[2 * o]);
        ob[(size_t)o * HH * WW + pA] = pv.x + a.x * gateA;
        ob[(size_t)o * HH * WW + pB] = pv.y + a.y * gateB;
    }
    #pragma unroll
    for (int c = OUTC; c < CHN; ++c) {
        float2 g = u2f(P[2 * c]);
        ob[(size_t)c * HH * WW + pA] = g.x;
        ob[(size_t)c * HH * WW + pB] = g.y;
    }
}

extern "C" void kernel_launch(void* const* d_in, const int* in_sizes, int n_in,
                              void* d_out, int out_size) {
    const float* x    = (const float*)d_in[0];
    const float* rnd  = (const float*)d_in[1];
    const float* w1_w = (const float*)d_in[2];
    const float* w1_b = (const float*)d_in[3];
    const float* w2_w = (const float*)d_in[4];
    float* out = (float*)d_out;

    dim3 grid(HH / 2, BB);
    dim3 block(WW);
    isoca_kernel<<<grid, block>>>(x, rnd, w1_w, w1_b, w2_w, out);
}

// round 4
// speedup vs baseline: 1.2107x; 1.0534x over previous
#include <cuda_runtime.h>
#include <cuda_bf16.h>
#include <stdint.h>
#include <math.h>

#define HH   256
#define WW   256
#define BB   16
#define CHN  12
#define OUTC 9
#define HID  128
#define PERC 36
#define KPAD 48           // 3 K-steps of 16 (col 36 = bias, rest zero)
#define TPB  128          // threads = pixels per block

// dynamic smem regions (bytes). rows are 128B, XOR-swizzled by granule.
#define R_AHI 0
#define R_ALO 16384
#define R_BHI 32768
#define R_BLO 49152
#define R_W2  65536                    // 128 cols * 80B (9 ull dup pairs + pad)
#define R_CEN (R_W2 + 128 * 80)       // 128 px * 13 f32 (12 centers + gate)
#define SM_TOTAL (R_CEN + 128 * 13 * 4)

#define SWG(row, g) ((g) ^ ((row) & 7) ^ (((row) >> 3) & 3))

typedef unsigned long long ull;

__device__ __forceinline__ uint32_t smem_u32(const void* p) {
    uint32_t a;
    asm("{ .reg .u64 t; cvta.to.shared.u64 t, %1; cvt.u32.u64 %0, t; }" : "=r"(a) : "l"(p));
    return a;
}
__device__ __forceinline__ void fma2(ull &d, ull a, ull b) {
    asm("fma.rn.f32x2 %0, %1, %2, %0;" : "+l"(d) : "l"(a), "l"(b));
}
__device__ __forceinline__ ull add2(ull a, ull b) {
    ull d; asm("add.rn.f32x2 %0, %1, %2;" : "=l"(d) : "l"(a), "l"(b)); return d;
}
__device__ __forceinline__ ull f2u(float lo, float hi) {
    ull d; asm("mov.b64 %0, {%1, %2};" : "=l"(d) : "f"(lo), "f"(hi)); return d;
}
__device__ __forceinline__ float2 u2f(ull v) {
    float2 r; asm("mov.b64 {%0, %1}, %2;" : "=f"(r.x), "=f"(r.y) : "l"(v)); return r;
}
__device__ __forceinline__ uint32_t pack_hi(float a, float b, float &ra, float &rb) {
    __nv_bfloat16 ha = __float2bfloat16_rn(a);
    __nv_bfloat16 hb = __float2bfloat16_rn(b);
    ra = a - __bfloat162float(ha);
    rb = b - __bfloat162float(hb);
    return (uint32_t)__bfloat16_as_ushort(ha) | ((uint32_t)__bfloat16_as_ushort(hb) << 16);
}
__device__ __forceinline__ uint32_t pack_bf(float a, float b) {
    return (uint32_t)__bfloat16_as_ushort(__float2bfloat16_rn(a))
         | ((uint32_t)__bfloat16_as_ushort(__float2bfloat16_rn(b)) << 16);
}
__device__ __forceinline__ void ldmx4(uint32_t r[4], uint32_t addr) {
    asm volatile("ldmatrix.sync.aligned.m8n8.x4.shared.b16 {%0,%1,%2,%3}, [%4];"
                 : "=r"(r[0]), "=r"(r[1]), "=r"(r[2]), "=r"(r[3]) : "r"(addr));
}
__device__ __forceinline__ void mma_bf16(float d[4], const uint32_t a[4],
                                         uint32_t b0, uint32_t b1) {
    asm volatile(
        "mma.sync.aligned.m16n8k16.row.col.f32.bf16.bf16.f32 "
        "{%0,%1,%2,%3}, {%4,%5,%6,%7}, {%8,%9}, {%0,%1,%2,%3};"
        : "+f"(d[0]), "+f"(d[1]), "+f"(d[2]), "+f"(d[3])
        : "r"(a[0]), "r"(a[1]), "r"(a[2]), "r"(a[3]), "r"(b0), "r"(b1));
}

// write one hi/lo row (48 padded vals) into a swizzled 128B-row region
__device__ __forceinline__ void store_row(char* smem, int reg_hi, int reg_lo,
                                          int row, const float* v) {
    #pragma unroll
    for (int g = 0; g < 6; ++g) {
        uint32_t hi[4], lo[4];
        #pragma unroll
        for (int j = 0; j < 4; ++j) {
            float ra, rb;
            hi[j] = pack_hi(v[8 * g + 2 * j], v[8 * g + 2 * j + 1], ra, rb);
            lo[j] = pack_bf(ra, rb);
        }
        int off = row * 128 + SWG(row, g) * 16;
        *(uint4*)(smem + reg_hi + off) = make_uint4(hi[0], hi[1], hi[2], hi[3]);
        *(uint4*)(smem + reg_lo + off) = make_uint4(lo[0], lo[1], lo[2], lo[3]);
    }
}

__global__ void __launch_bounds__(TPB) isoca_mma(
    const float* __restrict__ x,
    const float* __restrict__ rnd,
    const float* __restrict__ w1_w,
    const float* __restrict__ w1_b,
    const float* __restrict__ w2_w,
    float* __restrict__ out)
{
    extern __shared__ char smem[];
    const uint32_t sb = smem_u32(smem);
    const int tid = threadIdx.x;
    const int warp = tid >> 5, lane = tid & 31;

    // ---- stage B = w1 rows [n][k] hi/lo (n = tid), bias at k=36 ----
    {
        float v[KPAD];
        const float* wr = w1_w + tid * PERC;
        #pragma unroll
        for (int k = 0; k < KPAD; ++k)
            v[k] = (k < PERC) ? __ldg(wr + k) : ((k == PERC) ? __ldg(w1_b + tid) : 0.0f);
        store_row(smem, R_BHI, R_BLO, tid, v);
    }
    // ---- stage w2 duplicated pairs: w2d[col][o] = {w,w} ----
    for (int i = tid; i < HID * OUTC; i += TPB) {
        int col = i / OUTC, o = i - col * OUTC;
        float w = __ldg(w2_w + o * HID + col);
        *(ull*)(smem + R_W2 + col * 80 + o * 8) = f2u(w, w);
    }

    // ---- perception (1 px per thread) ----
    const int bx = blockIdx.x, h = blockIdx.y, b = blockIdx.z;
    const int wc = bx * TPB + tid;
    const int hm = (h + HH - 1) & (HH - 1);
    const int hp = (h + 1) & (HH - 1);
    const int wm = (wc + WW - 1) & (WW - 1);
    const int wp = (wc + 1) & (WW - 1);

    {
        float v[KPAD];
        float pool = 0.0f;
        const float* xb = x + (size_t)b * CHN * HH * WW;
        #pragma unroll
        for (int c = 0; c < CHN; ++c) {
            const float* xc = xb + (size_t)c * HH * WW;
            const float* rU = xc + hm * WW;
            const float* rC = xc + h * WW;
            const float* rD = xc + hp * WW;
            float n00 = __ldg(rU + wm), n01 = __ldg(rU + wc), n02 = __ldg(rU + wp);
            float n10 = __ldg(rC + wm), n11 = __ldg(rC + wc), n12 = __ldg(rC + wp);
            float n20 = __ldg(rD + wm), n21 = __ldg(rD + wc), n22 = __ldg(rD + wp);

            float lap = (n00 + n02 + n20 + n22) + 2.0f * (n01 + n10 + n12 + n21) - 12.0f * n11;
            float gx  = (n02 - n00) + 2.0f * (n12 - n10) + (n22 - n20);
            float gy  = (n20 - n00) + 2.0f * (n21 - n01) + (n22 - n02);

            v[2 * c]       = n11;
            v[2 * c + 1]   = lap;
            v[2 * CHN + c] = sqrtf(gx * gx + gy * gy + 1e-8f);

            if (c == 3) {
                bool tu = (h > 0), td = (h < HH - 1), tl = (wc > 0), tr = (wc < WW - 1);
                float p = n11;
                if (tu) p = fmaxf(p, n01);
                if (td) p = fmaxf(p, n21);
                if (tl) p = fmaxf(p, n10);
                if (tr) p = fmaxf(p, n12);
                if (tu && tl) p = fmaxf(p, n00);
                if (tu && tr) p = fmaxf(p, n02);
                if (td && tl) p = fmaxf(p, n20);
                if (td && tr) p = fmaxf(p, n22);
                pool = p;
            }
        }
        v[PERC] = 1.0f;                       // bias column
        #pragma unroll
        for (int k = PERC + 1; k < KPAD; ++k) v[k] = 0.0f;

        store_row(smem, R_AHI, R_ALO, tid, v);

        float rv = __ldg(rnd + ((size_t)b * HH + h) * WW + wc);
        float gate = floorf(rv + 0.5f) * ((pool > 0.1f) ? 1.0f : 0.0f);
        float* cen = (float*)(smem + R_CEN) + tid * 13;
        #pragma unroll
        for (int c = 0; c < CHN; ++c) cen[c] = v[2 * c];
        cen[12] = gate;
    }

    __syncthreads();

    // ---- load A fragments (2 M-tiles of 16 px, 3 K-steps, hi+lo) ----
    const int m = lane >> 3;
    uint32_t Ahi[2][3][4], Alo[2][3][4];
    #pragma unroll
    for (int mt = 0; mt < 2; ++mt) {
        int arow = warp * 32 + mt * 16 + (m & 1) * 8 + (lane & 7);
        #pragma unroll
        for (int ks = 0; ks < 3; ++ks) {
            int g = ks * 2 + (m >> 1);
            int off = arow * 128 + SWG(arow, g) * 16;
            ldmx4(Ahi[mt][ks], sb + R_AHI + off);
            ldmx4(Alo[mt][ks], sb + R_ALO + off);
        }
    }

    ull acc2[2][OUTC];
    #pragma unroll
    for (int mt = 0; mt < 2; ++mt)
        #pragma unroll
        for (int o = 0; o < OUTC; ++o) acc2[mt][o] = 0ull;

    const int brow_base = (m >> 1) * 8 + (lane & 7);

    #pragma unroll 2
    for (int np = 0; np < 8; ++np) {
        float D[2][2][4];
        #pragma unroll
        for (int mt = 0; mt < 2; ++mt)
            #pragma unroll
            for (int nt = 0; nt < 2; ++nt)
                #pragma unroll
                for (int i = 0; i < 4; ++i) D[mt][nt][i] = 0.0f;

        #pragma unroll
        for (int ks = 0; ks < 3; ++ks) {
            int brow = np * 16 + brow_base;
            int g = ks * 2 + (m & 1);
            int off = brow * 128 + SWG(brow, g) * 16;
            uint32_t bh[4], bl[4];
            ldmx4(bh, sb + R_BHI + off);
            ldmx4(bl, sb + R_BLO + off);
            #pragma unroll
            for (int mt = 0; mt < 2; ++mt) {
                mma_bf16(D[mt][0], Ahi[mt][ks], bh[0], bh[1]);
                mma_bf16(D[mt][1], Ahi[mt][ks], bh[2], bh[3]);
                mma_bf16(D[mt][0], Ahi[mt][ks], bl[0], bl[1]);
                mma_bf16(D[mt][1], Ahi[mt][ks], bl[2], bl[3]);
                mma_bf16(D[mt][0], Alo[mt][ks], bh[0], bh[1]);
                mma_bf16(D[mt][1], Alo[mt][ks], bh[2], bh[3]);
            }
        }

        // ---- layer 2 epilogue: relu + packed fp32x2 over this hidden block ----
        #pragma unroll
        for (int nt = 0; nt < 2; ++nt) {
            int c0 = np * 16 + nt * 8 + 2 * (lane & 3);
            const char* qa = smem + R_W2 + c0 * 80;
            const char* qb = qa + 80;
            ulonglong2 qa0 = *(const ulonglong2*)(qa);
            ulonglong2 qa1 = *(const ulonglong2*)(qa + 16);
            ulonglong2 qa2 = *(const ulonglong2*)(qa + 32);
            ulonglong2 qa3 = *(const ulonglong2*)(qa + 48);
            ull       qa4 = *(const ull*)(qa + 64);
            ulonglong2 qb0 = *(const ulonglong2*)(qb);
            ulonglong2 qb1 = *(const ulonglong2*)(qb + 16);
            ulonglong2 qb2 = *(const ulonglong2*)(qb + 32);
            ulonglong2 qb3 = *(const ulonglong2*)(qb + 48);
            ull       qb4 = *(const ull*)(qb + 64);
            #pragma unroll
            for (int mt = 0; mt < 2; ++mt) {
                float d0 = D[mt][nt][0], d1 = D[mt][nt][1];
                float d2 = D[mt][nt][2], d3 = D[mt][nt][3];
                d0 = fmaxf(d0, 0.0f) + 0.01f * fminf(d0, 0.0f);
                d1 = fmaxf(d1, 0.0f) + 0.01f * fminf(d1, 0.0f);
                d2 = fmaxf(d2, 0.0f) + 0.01f * fminf(d2, 0.0f);
                d3 = fmaxf(d3, 0.0f) + 0.01f * fminf(d3, 0.0f);
                ull p0 = f2u(d0, d2);      // col c0: rows {g, g+8}
                ull p1 = f2u(d1, d3);      // col c0+1
                fma2(acc2[mt][0], qa0.x, p0); fma2(acc2[mt][1], qa0.y, p0);
                fma2(acc2[mt][2], qa1.x, p0); fma2(acc2[mt][3], qa1.y, p0);
                fma2(acc2[mt][4], qa2.x, p0); fma2(acc2[mt][5], qa2.y, p0);
                fma2(acc2[mt][6], qa3.x, p0); fma2(acc2[mt][7], qa3.y, p0);
                fma2(acc2[mt][8], qa4,   p0);
                fma2(acc2[mt][0], qb0.x, p1); fma2(acc2[mt][1], qb0.y, p1);
                fma2(acc2[mt][2], qb1.x, p1); fma2(acc2[mt][3], qb1.y, p1);
                fma2(acc2[mt][4], qb2.x, p1); fma2(acc2[mt][5], qb2.y, p1);
                fma2(acc2[mt][6], qb3.x, p1); fma2(acc2[mt][7], qb3.y, p1);
                fma2(acc2[mt][8], qb4,   p1);
            }
        }
    }

    // ---- reduce over the 4 lanes of each row-group quad ----
    #pragma unroll
    for (int mt = 0; mt < 2; ++mt)
        #pragma unroll
        for (int o = 0; o < OUTC; ++o) {
            ull v = acc2[mt][o];
            v = add2(v, __shfl_xor_sync(0xffffffffu, v, 1));
            v = add2(v, __shfl_xor_sync(0xffffffffu, v, 2));
            acc2[mt][o] = v;
        }

    // ---- write: lane%4==0 -> row g (lo half), lane%4==1 -> row g+8 (hi half) ----
    const int sel = lane & 3;
    if (sel < 2) {
        const int g = lane >> 2;
        #pragma unroll
        for (int mt = 0; mt < 2; ++mt) {
            int pxl = warp * 32 + mt * 16 + g + 8 * sel;
            const float* cen = (const float*)(smem + R_CEN) + pxl * 13;
            float gate = cen[12];
            float* ob = out + (size_t)b * CHN * HH * WW + (size_t)h * WW + bx * TPB + pxl;
            #pragma unroll
            for (int o = 0; o < OUTC; ++o) {
                float2 p = u2f(acc2[mt][o]);
                float y = sel ? p.y : p.x;
                ob[(size_t)o * HH * WW] = cen[o] + y * gate;
            }
            #pragma unroll
            for (int c = OUTC; c < CHN; ++c)
                ob[(size_t)c * HH * WW] = cen[c];
        }
    }
}

extern "C" void kernel_launch(void* const* d_in, const int* in_sizes, int n_in,
                              void* d_out, int out_size) {
    const float* x    = (const float*)d_in[0];
    const float* rnd  = (const float*)d_in[1];
    const float* w1_w = (const float*)d_in[2];
    const float* w1_b = (const float*)d_in[3];
    const float* w2_w = (const float*)d_in[4];
    float* out = (float*)d_out;

    cudaFuncSetAttribute(isoca_mma, cudaFuncAttributeMaxDynamicSharedMemorySize, SM_TOTAL);
    dim3 grid(WW / TPB, HH, BB);
    isoca_mma<<<grid, TPB, SM_TOTAL>>>(x, rnd, w1_w, w1_b, w2_w, out);
}

// round 5
// speedup vs baseline: 1.2204x; 1.0080x over previous
#include <cuda_runtime.h>
#include <cuda_bf16.h>
#include <stdint.h>
#include <math.h>

#define HH   256
#define WW   256
#define BB   16
#define CHN  12
#define OUTC 9
#define HID  128
#define PERC 36
#define KPAD 48           // 3 K-steps of 16 (col 36 = bias, rest zero)
#define TPB  128          // threads = pixels per block

// dynamic smem regions (bytes). rows are 128B, XOR-swizzled by granule.
#define R_AHI 0
#define R_ALO 16384
#define R_BHI 32768
#define R_BLO 49152
#define R_W2  65536                    // 128 cols * 80B (9 ull dup pairs + pad)
#define R_CEN (R_W2 + 128 * 80)       // 128 px * 13 f32 (12 centers + gate)
#define SM_TOTAL (R_CEN + 128 * 13 * 4)

#define SWG(row, g) ((g) ^ ((row) & 7) ^ (((row) >> 3) & 3))

typedef unsigned long long ull;

__device__ __forceinline__ uint32_t smem_u32(const void* p) {
    uint32_t a;
    asm("{ .reg .u64 t; cvta.to.shared.u64 t, %1; cvt.u32.u64 %0, t; }" : "=r"(a) : "l"(p));
    return a;
}
__device__ __forceinline__ void fma2(ull &d, ull a, ull b) {
    asm("fma.rn.f32x2 %0, %1, %2, %0;" : "+l"(d) : "l"(a), "l"(b));
}
__device__ __forceinline__ ull add2(ull a, ull b) {
    ull d; asm("add.rn.f32x2 %0, %1, %2;" : "=l"(d) : "l"(a), "l"(b)); return d;
}
__device__ __forceinline__ ull f2u(float lo, float hi) {
    ull d; asm("mov.b64 %0, {%1, %2};" : "=l"(d) : "f"(lo), "f"(hi)); return d;
}
__device__ __forceinline__ float2 u2f(ull v) {
    float2 r; asm("mov.b64 {%0, %1}, %2;" : "=f"(r.x), "=f"(r.y) : "l"(v)); return r;
}
__device__ __forceinline__ uint32_t pack_hi(float a, float b, float &ra, float &rb) {
    __nv_bfloat16 ha = __float2bfloat16_rn(a);
    __nv_bfloat16 hb = __float2bfloat16_rn(b);
    ra = a - __bfloat162float(ha);
    rb = b - __bfloat162float(hb);
    return (uint32_t)__bfloat16_as_ushort(ha) | ((uint32_t)__bfloat16_as_ushort(hb) << 16);
}
__device__ __forceinline__ uint32_t pack_bf(float a, float b) {
    return (uint32_t)__bfloat16_as_ushort(__float2bfloat16_rn(a))
         | ((uint32_t)__bfloat16_as_ushort(__float2bfloat16_rn(b)) << 16);
}
__device__ __forceinline__ void ldmx4(uint32_t r[4], uint32_t addr) {
    asm volatile("ldmatrix.sync.aligned.m8n8.x4.shared.b16 {%0,%1,%2,%3}, [%4];"
                 : "=r"(r[0]), "=r"(r[1]), "=r"(r[2]), "=r"(r[3]) : "r"(addr));
}
__device__ __forceinline__ void mma_bf16(float d[4], const uint32_t a[4],
                                         uint32_t b0, uint32_t b1) {
    asm volatile(
        "mma.sync.aligned.m16n8k16.row.col.f32.bf16.bf16.f32 "
        "{%0,%1,%2,%3}, {%4,%5,%6,%7}, {%8,%9}, {%0,%1,%2,%3};"
        : "+f"(d[0]), "+f"(d[1]), "+f"(d[2]), "+f"(d[3])
        : "r"(a[0]), "r"(a[1]), "r"(a[2]), "r"(a[3]), "r"(b0), "r"(b1));
}

// write one hi/lo row (48 padded vals) into a swizzled 128B-row region
__device__ __forceinline__ void store_row(char* smem, int reg_hi, int reg_lo,
                                          int row, const float* v) {
    #pragma unroll
    for (int g = 0; g < 6; ++g) {
        uint32_t hi[4], lo[4];
        #pragma unroll
        for (int j = 0; j < 4; ++j) {
            float ra, rb;
            hi[j] = pack_hi(v[8 * g + 2 * j], v[8 * g + 2 * j + 1], ra, rb);
            lo[j] = pack_bf(ra, rb);
        }
        int off = row * 128 + SWG(row, g) * 16;
        *(uint4*)(smem + reg_hi + off) = make_uint4(hi[0], hi[1], hi[2], hi[3]);
        *(uint4*)(smem + reg_lo + off) = make_uint4(lo[0], lo[1], lo[2], lo[3]);
    }
}

__global__ void __launch_bounds__(TPB) isoca_mma(
    const float* __restrict__ x,
    const float* __restrict__ rnd,
    const float* __restrict__ w1_w,
    const float* __restrict__ w1_b,
    const float* __restrict__ w2_w,
    float* __restrict__ out)
{
    extern __shared__ char smem[];
    const uint32_t sb = smem_u32(smem);
    const int tid = threadIdx.x;
    const int warp = tid >> 5, lane = tid & 31;

    // ---- stage B = w1 rows [n][k] hi/lo (n = tid), bias at k=36 ----
    {
        float v[KPAD];
        const float* wr = w1_w + tid * PERC;
        #pragma unroll
        for (int k = 0; k < KPAD; ++k)
            v[k] = (k < PERC) ? __ldg(wr + k) : ((k == PERC) ? __ldg(w1_b + tid) : 0.0f);
        store_row(smem, R_BHI, R_BLO, tid, v);
    }
    // ---- stage w2 duplicated pairs: w2d[col][o] = {w,w} ----
    for (int i = tid; i < HID * OUTC; i += TPB) {
        int col = i / OUTC, o = i - col * OUTC;
        float w = __ldg(w2_w + o * HID + col);
        *(ull*)(smem + R_W2 + col * 80 + o * 8) = f2u(w, w);
    }

    // ---- perception (1 px per thread) ----
    const int bx = blockIdx.x, h = blockIdx.y, b = blockIdx.z;
    const int wc = bx * TPB + tid;
    const int hm = (h + HH - 1) & (HH - 1);
    const int hp = (h + 1) & (HH - 1);
    const int wm = (wc + WW - 1) & (WW - 1);
    const int wp = (wc + 1) & (WW - 1);

    {
        float v[KPAD];
        float pool = 0.0f;
        const float* xb = x + (size_t)b * CHN * HH * WW;
        #pragma unroll
        for (int c = 0; c < CHN; ++c) {
            const float* xc = xb + (size_t)c * HH * WW;
            const float* rU = xc + hm * WW;
            const float* rC = xc + h * WW;
            const float* rD = xc + hp * WW;
            float n00 = __ldg(rU + wm), n01 = __ldg(rU + wc), n02 = __ldg(rU + wp);
            float n10 = __ldg(rC + wm), n11 = __ldg(rC + wc), n12 = __ldg(rC + wp);
            float n20 = __ldg(rD + wm), n21 = __ldg(rD + wc), n22 = __ldg(rD + wp);

            float lap = (n00 + n02 + n20 + n22) + 2.0f * (n01 + n10 + n12 + n21) - 12.0f * n11;
            float gx  = (n02 - n00) + 2.0f * (n12 - n10) + (n22 - n20);
            float gy  = (n20 - n00) + 2.0f * (n21 - n01) + (n22 - n02);

            v[2 * c]       = n11;
            v[2 * c + 1]   = lap;
            v[2 * CHN + c] = sqrtf(gx * gx + gy * gy + 1e-8f);

            if (c == 3) {
                bool tu = (h > 0), td = (h < HH - 1), tl = (wc > 0), tr = (wc < WW - 1);
                float p = n11;
                if (tu) p = fmaxf(p, n01);
                if (td) p = fmaxf(p, n21);
                if (tl) p = fmaxf(p, n10);
                if (tr) p = fmaxf(p, n12);
                if (tu && tl) p = fmaxf(p, n00);
                if (tu && tr) p = fmaxf(p, n02);
                if (td && tl) p = fmaxf(p, n20);
                if (td && tr) p = fmaxf(p, n22);
                pool = p;
            }
        }
        v[PERC] = 1.0f;                       // bias column
        #pragma unroll
        for (int k = PERC + 1; k < KPAD; ++k) v[k] = 0.0f;

        store_row(smem, R_AHI, R_ALO, tid, v);

        float rv = __ldg(rnd + ((size_t)b * HH + h) * WW + wc);
        float gate = floorf(rv + 0.5f) * ((pool > 0.1f) ? 1.0f : 0.0f);
        float* cen = (float*)(smem + R_CEN) + tid * 13;
        #pragma unroll
        for (int c = 0; c < CHN; ++c) cen[c] = v[2 * c];
        cen[12] = gate;
    }

    __syncthreads();

    // ---- load A fragments (2 M-tiles of 16 px, 3 K-steps, hi+lo) ----
    const int m = lane >> 3;
    uint32_t Ahi[2][3][4], Alo[2][3][4];
    #pragma unroll
    for (int mt = 0; mt < 2; ++mt) {
        int arow = warp * 32 + mt * 16 + (m & 1) * 8 + (lane & 7);
        #pragma unroll
        for (int ks = 0; ks < 3; ++ks) {
            int g = ks * 2 + (m >> 1);
            int off = arow * 128 + SWG(arow, g) * 16;
            ldmx4(Ahi[mt][ks], sb + R_AHI + off);
            ldmx4(Alo[mt][ks], sb + R_ALO + off);
        }
    }

    ull acc2[2][OUTC];
    #pragma unroll
    for (int mt = 0; mt < 2; ++mt)
        #pragma unroll
        for (int o = 0; o < OUTC; ++o) acc2[mt][o] = 0ull;

    const int brow_base = (m >> 1) * 8 + (lane & 7);

    #pragma unroll 2
    for (int np = 0; np < 8; ++np) {
        float D[2][2][4];
        #pragma unroll
        for (int mt = 0; mt < 2; ++mt)
            #pragma unroll
            for (int nt = 0; nt < 2; ++nt)
                #pragma unroll
                for (int i = 0; i < 4; ++i) D[mt][nt][i] = 0.0f;

        #pragma unroll
        for (int ks = 0; ks < 3; ++ks) {
            int brow = np * 16 + brow_base;
            int g = ks * 2 + (m & 1);
            int off = brow * 128 + SWG(brow, g) * 16;
            uint32_t bh[4], bl[4];
            ldmx4(bh, sb + R_BHI + off);
            ldmx4(bl, sb + R_BLO + off);
            #pragma unroll
            for (int mt = 0; mt < 2; ++mt) {
                mma_bf16(D[mt][0], Ahi[mt][ks], bh[0], bh[1]);
                mma_bf16(D[mt][1], Ahi[mt][ks], bh[2], bh[3]);
                mma_bf16(D[mt][0], Ahi[mt][ks], bl[0], bl[1]);
                mma_bf16(D[mt][1], Ahi[mt][ks], bl[2], bl[3]);
                mma_bf16(D[mt][0], Alo[mt][ks], bh[0], bh[1]);
                mma_bf16(D[mt][1], Alo[mt][ks], bh[2], bh[3]);
            }
        }

        // ---- layer 2 epilogue: relu + packed fp32x2 over this hidden block ----
        #pragma unroll
        for (int nt = 0; nt < 2; ++nt) {
            int c0 = np * 16 + nt * 8 + 2 * (lane & 3);
            const char* qa = smem + R_W2 + c0 * 80;
            const char* qb = qa + 80;
            ulonglong2 qa0 = *(const ulonglong2*)(qa);
            ulonglong2 qa1 = *(const ulonglong2*)(qa + 16);
            ulonglong2 qa2 = *(const ulonglong2*)(qa + 32);
            ulonglong2 qa3 = *(const ulonglong2*)(qa + 48);
            ull       qa4 = *(const ull*)(qa + 64);
            ulonglong2 qb0 = *(const ulonglong2*)(qb);
            ulonglong2 qb1 = *(const ulonglong2*)(qb + 16);
            ulonglong2 qb2 = *(const ulonglong2*)(qb + 32);
            ulonglong2 qb3 = *(const ulonglong2*)(qb + 48);
            ull       qb4 = *(const ull*)(qb + 64);
            #pragma unroll
            for (int mt = 0; mt < 2; ++mt) {
                float d0 = D[mt][nt][0], d1 = D[mt][nt][1];
                float d2 = D[mt][nt][2], d3 = D[mt][nt][3];
                d0 = fmaxf(d0, 0.0f) + 0.01f * fminf(d0, 0.0f);
                d1 = fmaxf(d1, 0.0f) + 0.01f * fminf(d1, 0.0f);
                d2 = fmaxf(d2, 0.0f) + 0.01f * fminf(d2, 0.0f);
                d3 = fmaxf(d3, 0.0f) + 0.01f * fminf(d3, 0.0f);
                ull p0 = f2u(d0, d2);      // col c0: rows {g, g+8}
                ull p1 = f2u(d1, d3);      // col c0+1
                fma2(acc2[mt][0], qa0.x, p0); fma2(acc2[mt][1], qa0.y, p0);
                fma2(acc2[mt][2], qa1.x, p0); fma2(acc2[mt][3], qa1.y, p0);
                fma2(acc2[mt][4], qa2.x, p0); fma2(acc2[mt][5], qa2.y, p0);
                fma2(acc2[mt][6], qa3.x, p0); fma2(acc2[mt][7], qa3.y, p0);
                fma2(acc2[mt][8], qa4,   p0);
                fma2(acc2[mt][0], qb0.x, p1); fma2(acc2[mt][1], qb0.y, p1);
                fma2(acc2[mt][2], qb1.x, p1); fma2(acc2[mt][3], qb1.y, p1);
                fma2(acc2[mt][4], qb2.x, p1); fma2(acc2[mt][5], qb2.y, p1);
                fma2(acc2[mt][6], qb3.x, p1); fma2(acc2[mt][7], qb3.y, p1);
                fma2(acc2[mt][8], qb4,   p1);
            }
        }
    }

    // ---- reduce over the 4 lanes of each row-group quad ----
    #pragma unroll
    for (int mt = 0; mt < 2; ++mt)
        #pragma unroll
        for (int o = 0; o < OUTC; ++o) {
            ull v = acc2[mt][o];
            v = add2(v, __shfl_xor_sync(0xffffffffu, v, 1));
            v = add2(v, __shfl_xor_sync(0xffffffffu, v, 2));
            acc2[mt][o] = v;
        }

    // ---- write: lane%4==0 -> row g (lo half), lane%4==1 -> row g+8 (hi half) ----
    const int sel = lane & 3;
    if (sel < 2) {
        const int g = lane >> 2;
        #pragma unroll
        for (int mt = 0; mt < 2; ++mt) {
            int pxl = warp * 32 + mt * 16 + g + 8 * sel;
            const float* cen = (const float*)(smem + R_CEN) + pxl * 13;
            float gate = cen[12];
            float* ob = out + (size_t)b * CHN * HH * WW + (size_t)h * WW + bx * TPB + pxl;
            #pragma unroll
            for (int o = 0; o < OUTC; ++o) {
                float2 p = u2f(acc2[mt][o]);
                float y = sel ? p.y : p.x;
                ob[(size_t)o * HH * WW] = cen[o] + y * gate;
            }
            #pragma unroll
            for (int c = OUTC; c < CHN; ++c)
                ob[(size_t)c * HH * WW] = cen[c];
        }
    }
}

extern "C" void kernel_launch(void* const* d_in, const int* in_sizes, int n_in,
                              void* d_out, int out_size) {
    const float* x    = (const float*)d_in[0];
    const float* rnd  = (const float*)d_in[1];
    const float* w1_w = (const float*)d_in[2];
    const float* w1_b = (const float*)d_in[3];
    const float* w2_w = (const float*)d_in[4];
    float* out = (float*)d_out;

    cudaFuncSetAttribute(isoca_mma, cudaFuncAttributeMaxDynamicSharedMemorySize, SM_TOTAL);
    dim3 grid(WW / TPB, HH, BB);
    isoca_mma<<<grid, TPB, SM_TOTAL>>>(x, rnd, w1_w, w1_b, w2_w, out);
}